// round 6
// baseline (speedup 1.0000x reference)
#include <cuda_runtime.h>

#define NP     32768
#define HIDN   100
#define NSTEPS 100

// ---------------------------------------------------------------------------
// Encoder: h1 = swish(x@We1+be1); h2 = swish(h1@We2+be2);
//          mu_zx = h2@Wmu+bmu ; log_t_zx = h2@Wlt+blt
// writes mu_zx at out[8N + 2p], log_t_zx at out[10N + p]
// ---------------------------------------------------------------------------
__global__ void __launch_bounds__(128) encoder_kernel(
    const float* __restrict__ x,
    const float* __restrict__ We1, const float* __restrict__ be1,
    const float* __restrict__ We2, const float* __restrict__ be2,
    const float* __restrict__ Wmu, const float* __restrict__ bmu,
    const float* __restrict__ Wlt, const float* __restrict__ blt,
    float* __restrict__ out)
{
    extern __shared__ float sm[];
    float* sWe2 = sm;             // 10000
    float* sWe1 = sm + 10000;     // 300
    float* sbe1 = sm + 10300;     // 100
    float* sbe2 = sm + 10400;     // 100
    float* sWmu = sm + 10500;     // 200
    float* sWlt = sm + 10700;     // 100
    float* sh1  = sm + 10800;     // 128*101

    const int tid = threadIdx.x;
    for (int i = tid; i < HIDN * HIDN; i += 128) sWe2[i] = We2[i];
    for (int i = tid; i < 3 * HIDN; i += 128)    sWe1[i] = We1[i];
    if (tid < HIDN) {
        sbe1[tid] = be1[tid];
        sbe2[tid] = be2[tid];
        sWlt[tid] = Wlt[tid];
    }
    for (int i = tid; i < HIDN * 2; i += 128) sWmu[i] = Wmu[i];
    __syncthreads();

    const int p = blockIdx.x * 128 + tid;
    const float x0 = x[3 * p + 0];
    const float x1 = x[3 * p + 1];
    const float x2 = x[3 * p + 2];

    float* h1 = sh1 + tid * (HIDN + 1);   // stride 101: conflict-free across lanes

    #pragma unroll 4
    for (int k = 0; k < HIDN; k++) {
        float a = sbe1[k];
        a = fmaf(x0, sWe1[k], a);
        a = fmaf(x1, sWe1[HIDN + k], a);
        a = fmaf(x2, sWe1[2 * HIDN + k], a);
        float sig = __fdividef(1.f, 1.f + __expf(-a));
        h1[k] = a * sig;
    }
    // each thread reads only its own h1 row -> no barrier needed

    float mu0 = bmu[0], mu1 = bmu[1], ltv = blt[0];
    for (int k = 0; k < HIDN; k++) {
        float a = sbe2[k];
        const float* w = sWe2 + k;   // column k, stride HIDN (broadcast across lanes)
        #pragma unroll 4
        for (int j = 0; j < HIDN; j++)
            a = fmaf(h1[j], w[j * HIDN], a);
        float sig = __fdividef(1.f, 1.f + __expf(-a));
        float h2 = a * sig;
        mu0 = fmaf(h2, sWmu[2 * k + 0], mu0);
        mu1 = fmaf(h2, sWmu[2 * k + 1], mu1);
        ltv = fmaf(h2, sWlt[k], ltv);
    }

    out[8 * NP + 2 * p + 0] = mu0;
    out[8 * NP + 2 * p + 1] = mu1;
    out[10 * NP + p]        = ltv;
}

// ---------------------------------------------------------------------------
// SDE kernel v2: 4 lanes cooperate per point. Each lane accumulates the
// J / B moment sums over j = lane_r + 4t (t < 25), then a 4-lane butterfly
// reduction assembles the full sums; the 2x2 geometry epilogue is computed
// redundantly in all 4 lanes (keeps z in sync with zero extra warp-instrs).
// ---------------------------------------------------------------------------
__global__ void __launch_bounds__(256) sde_kernel(
    const float* __restrict__ Wd1,  const float* __restrict__ bd1,
    const float* __restrict__ Wdmu, const float* __restrict__ bdmu,
    const float* __restrict__ Wds,  const float* __restrict__ bds,
    const float* __restrict__ b_muz, const float* __restrict__ b_ltz,
    const float* __restrict__ noise,
    float* __restrict__ out)
{
    // Per-hidden-unit constant table (12 floats each, packed as 3x float4):
    // cA = {u0, u1, b, u0*u0}; cB = {u0*u1, u1*u1, wmu0, wmu1};
    // cC = {wmu2, ws0, ws1, ws2}
    __shared__ float4 cA[HIDN], cB[HIDN], cC[HIDN];

    const int tid = threadIdx.x;
    for (int j = tid; j < HIDN; j += 256) {
        float u0 = Wd1[j];
        float u1 = Wd1[HIDN + j];
        float b  = bd1[j];
        cA[j] = make_float4(u0, u1, b, u0 * u0);
        cB[j] = make_float4(u0 * u1, u1 * u1, Wdmu[j * 3 + 0], Wdmu[j * 3 + 1]);
        cC[j] = make_float4(Wdmu[j * 3 + 2], Wds[j * 3 + 0], Wds[j * 3 + 1], Wds[j * 3 + 2]);
    }
    __syncthreads();

    const int r = tid & 3;                      // lane within point group
    const int p = blockIdx.x * 64 + (tid >> 2); // point index

    float z0 = out[8 * NP + 2 * p + 0];   // broadcast across the 4 lanes
    float z1 = out[8 * NP + 2 * p + 1];
    const float ltv  = out[10 * NP + p];
    const float sqdt = sqrtf(__expf(2.f * ltv) * (1.0f / NSTEPS));

    const float2* __restrict__ noise2 = (const float2*)noise;

    for (int s = 0; s < NSTEPS; s++) {
        // Partial sums over this lane's j subset:
        // J[i][l]  = sum_j w_ji * swish'(a_j) * u_lj
        // Bm[i][q] = sum_j w_ji * swish''(a_j) * (u u^T)_q   (q: 00,01,11)
        float J[6][2];
        float Bm[6][3];
        #pragma unroll
        for (int i = 0; i < 6; i++) {
            J[i][0] = 0.f; J[i][1] = 0.f;
            Bm[i][0] = 0.f; Bm[i][1] = 0.f; Bm[i][2] = 0.f;
        }

        #pragma unroll 5
        for (int t = 0; t < HIDN / 4; t++) {
            const int j = r + 4 * t;
            const float4 a4 = cA[j];
            const float4 b4 = cB[j];
            const float4 c4 = cC[j];
            float a   = fmaf(z0, a4.x, fmaf(z1, a4.y, a4.z));
            float sig = __fdividef(1.f, 1.f + __expf(-a));
            float t1  = sig * (1.f - sig);
            float d   = fmaf(a, t1, sig);                       // swish'
            float e   = t1 * fmaf(a, 1.f - 2.f * sig, 2.f);     // swish''
            float du0 = d * a4.x;
            float du1 = d * a4.y;
            float e00 = e * a4.w;
            float e01 = e * b4.x;
            float e11 = e * b4.y;
            float w[6] = { b4.z, b4.w, c4.x, c4.y, c4.z, c4.w };
            #pragma unroll
            for (int i = 0; i < 6; i++) {
                J[i][0]  = fmaf(w[i], du0, J[i][0]);
                J[i][1]  = fmaf(w[i], du1, J[i][1]);
                Bm[i][0] = fmaf(w[i], e00, Bm[i][0]);
                Bm[i][1] = fmaf(w[i], e01, Bm[i][1]);
                Bm[i][2] = fmaf(w[i], e11, Bm[i][2]);
            }
        }

        // Butterfly reduce across the 4 lanes of this point (deterministic,
        // identical result in every lane).
        #pragma unroll
        for (int i = 0; i < 6; i++) {
            #pragma unroll
            for (int l = 0; l < 2; l++) {
                J[i][l] += __shfl_xor_sync(0xffffffffu, J[i][l], 1);
                J[i][l] += __shfl_xor_sync(0xffffffffu, J[i][l], 2);
            }
            #pragma unroll
            for (int q = 0; q < 3; q++) {
                Bm[i][q] += __shfl_xor_sync(0xffffffffu, Bm[i][q], 1);
                Bm[i][q] += __shfl_xor_sync(0xffffffffu, Bm[i][q], 2);
            }
        }

        // G and Dg[k][m][l] = dG[k,m]/dz_l  (all lanes redundantly)
        float g00 = 0.f, g01 = 0.f, g11 = 0.f;
        float Dg[2][2][2];
        #pragma unroll
        for (int k = 0; k < 2; k++)
            #pragma unroll
            for (int m = 0; m < 2; m++)
                #pragma unroll
                for (int l = 0; l < 2; l++)
                    Dg[k][m][l] = 0.f;

        #pragma unroll
        for (int i = 0; i < 6; i++) {
            g00 = fmaf(J[i][0], J[i][0], g00);
            g01 = fmaf(J[i][0], J[i][1], g01);
            g11 = fmaf(J[i][1], J[i][1], g11);
            #pragma unroll
            for (int k = 0; k < 2; k++)
                #pragma unroll
                for (int m = 0; m < 2; m++)
                    #pragma unroll
                    for (int l = 0; l < 2; l++)
                        Dg[k][m][l] += Bm[i][k + l] * J[i][m] + J[i][k] * Bm[i][m + l];
        }

        const float detg = fmaf(g00, g11, -g01 * g01);
        const float rin  = __fdividef(1.f, detg);
        float gi[2][2];
        gi[0][0] =  g11 * rin;
        gi[0][1] = -g01 * rin;
        gi[1][0] = -g01 * rin;
        gi[1][1] =  g00 * rin;

        // Christoffel: Ch[i][k][l] = 0.5*sum_m gi[i][m]*(Dg[k][m][l]+Dg[l][m][k]-Dg[k][l][m])
        float Ch[2][2][2];
        #pragma unroll
        for (int i = 0; i < 2; i++)
            #pragma unroll
            for (int k = 0; k < 2; k++)
                #pragma unroll
                for (int l = 0; l < 2; l++) {
                    float sacc = 0.f;
                    #pragma unroll
                    for (int m = 0; m < 2; m++)
                        sacc += gi[i][m] * (Dg[k][m][l] + Dg[l][m][k] - Dg[k][l][m]);
                    Ch[i][k][l] = 0.5f * sacc;
                }

        // drift[i] = 0.5 * sum_{j,k} gi[j][k] * Ch[i][j][k]
        float drift[2];
        #pragma unroll
        for (int i = 0; i < 2; i++) {
            float sacc = 0.f;
            #pragma unroll
            for (int jj = 0; jj < 2; jj++)
                #pragma unroll
                for (int kk = 0; kk < 2; kk++)
                    sacc += gi[jj][kk] * Ch[i][jj][kk];
            drift[i] = 0.5f * sacc;
        }

        const float2 nz = noise2[s * NP + p];   // same addr in 4 lanes -> broadcast
        const float dW0 = sqdt * nz.x;
        const float dW1 = sqdt * nz.y;

        z0 += drift[0] + gi[0][0] * dW0 + gi[0][1] * dW1;
        z1 += drift[1] + gi[1][0] * dW0 + gi[1][1] * dW1;
    }

    // Final decoder heads at z: partial sums on own j subset, then reduce.
    float mu[3] = { 0.f, 0.f, 0.f };
    float ls[3] = { 0.f, 0.f, 0.f };
    #pragma unroll 5
    for (int t = 0; t < HIDN / 4; t++) {
        const int j = r + 4 * t;
        const float4 a4 = cA[j];
        const float4 b4 = cB[j];
        const float4 c4 = cC[j];
        float a   = fmaf(z0, a4.x, fmaf(z1, a4.y, a4.z));
        float sig = __fdividef(1.f, 1.f + __expf(-a));
        float h   = a * sig;
        mu[0] = fmaf(h, b4.z, mu[0]);
        mu[1] = fmaf(h, b4.w, mu[1]);
        mu[2] = fmaf(h, c4.x, mu[2]);
        ls[0] = fmaf(h, c4.y, ls[0]);
        ls[1] = fmaf(h, c4.z, ls[1]);
        ls[2] = fmaf(h, c4.w, ls[2]);
    }
    #pragma unroll
    for (int i = 0; i < 3; i++) {
        mu[i] += __shfl_xor_sync(0xffffffffu, mu[i], 1);
        mu[i] += __shfl_xor_sync(0xffffffffu, mu[i], 2);
        ls[i] += __shfl_xor_sync(0xffffffffu, ls[i], 1);
        ls[i] += __shfl_xor_sync(0xffffffffu, ls[i], 2);
    }

    if (r == 0) {
        // Outputs (tuple concatenation, 14*NP floats):
        // z | mu_xz | log_sigma_xz | mu_zx | log_t_zx | mu_z | log_t_z
        out[2 * p + 0] = z0;
        out[2 * p + 1] = z1;
        out[2 * NP + 3 * p + 0] = mu[0] + bdmu[0];
        out[2 * NP + 3 * p + 1] = mu[1] + bdmu[1];
        out[2 * NP + 3 * p + 2] = mu[2] + bdmu[2];
        out[5 * NP + 3 * p + 0] = ls[0] + bds[0];
        out[5 * NP + 3 * p + 1] = ls[1] + bds[1];
        out[5 * NP + 3 * p + 2] = ls[2] + bds[2];
        out[11 * NP + 2 * p + 0] = b_muz[0];
        out[11 * NP + 2 * p + 1] = b_muz[1];
        out[13 * NP + p] = b_ltz[0];
    }
}

extern "C" void kernel_launch(void* const* d_in, const int* in_sizes, int n_in,
                              void* d_out, int out_size)
{
    const float* x     = (const float*)d_in[0];
    const float* We1   = (const float*)d_in[1];
    const float* be1   = (const float*)d_in[2];
    const float* We2   = (const float*)d_in[3];
    const float* be2   = (const float*)d_in[4];
    const float* Wmu   = (const float*)d_in[5];
    const float* bmu   = (const float*)d_in[6];
    const float* Wlt   = (const float*)d_in[7];
    const float* blt   = (const float*)d_in[8];
    const float* Wd1   = (const float*)d_in[9];
    const float* bd1   = (const float*)d_in[10];
    const float* Wdmu  = (const float*)d_in[11];
    const float* bdmu  = (const float*)d_in[12];
    const float* Wds   = (const float*)d_in[13];
    const float* bds   = (const float*)d_in[14];
    const float* b_muz = (const float*)d_in[15];
    const float* b_ltz = (const float*)d_in[16];
    const float* noise = (const float*)d_in[17];
    float* out = (float*)d_out;

    const size_t smem = (size_t)(10800 + 128 * (HIDN + 1)) * sizeof(float); // ~94.9 KB
    cudaFuncSetAttribute(encoder_kernel,
                         cudaFuncAttributeMaxDynamicSharedMemorySize, (int)smem);

    encoder_kernel<<<NP / 128, 128, smem>>>(x, We1, be1, We2, be2,
                                            Wmu, bmu, Wlt, blt, out);
    // 4 lanes per point: 64 points per 256-thread block -> 512 blocks
    sde_kernel<<<NP / 64, 256>>>(Wd1, bd1, Wdmu, bdmu, Wds, bds,
                                 b_muz, b_ltz, noise, out);
}

// round 7
// speedup vs baseline: 1.7409x; 1.7409x over previous
#include <cuda_runtime.h>

#define NP     32768
#define HIDN   100
#define NSTEPS 100

// ---------------------------------------------------------------------------
// Encoder: h1 = swish(x@We1+be1); h2 = swish(h1@We2+be2);
//          mu_zx = h2@Wmu+bmu ; log_t_zx = h2@Wlt+blt
// writes mu_zx at out[8N + 2p], log_t_zx at out[10N + p]
// ---------------------------------------------------------------------------
__global__ void __launch_bounds__(128) encoder_kernel(
    const float* __restrict__ x,
    const float* __restrict__ We1, const float* __restrict__ be1,
    const float* __restrict__ We2, const float* __restrict__ be2,
    const float* __restrict__ Wmu, const float* __restrict__ bmu,
    const float* __restrict__ Wlt, const float* __restrict__ blt,
    float* __restrict__ out)
{
    extern __shared__ float sm[];
    float* sWe2 = sm;             // 10000
    float* sWe1 = sm + 10000;     // 300
    float* sbe1 = sm + 10300;     // 100
    float* sbe2 = sm + 10400;     // 100
    float* sWmu = sm + 10500;     // 200
    float* sWlt = sm + 10700;     // 100
    float* sh1  = sm + 10800;     // 128*101

    const int tid = threadIdx.x;
    for (int i = tid; i < HIDN * HIDN; i += 128) sWe2[i] = We2[i];
    for (int i = tid; i < 3 * HIDN; i += 128)    sWe1[i] = We1[i];
    if (tid < HIDN) {
        sbe1[tid] = be1[tid];
        sbe2[tid] = be2[tid];
        sWlt[tid] = Wlt[tid];
    }
    for (int i = tid; i < HIDN * 2; i += 128) sWmu[i] = Wmu[i];
    __syncthreads();

    const int p = blockIdx.x * 128 + tid;
    const float x0 = x[3 * p + 0];
    const float x1 = x[3 * p + 1];
    const float x2 = x[3 * p + 2];

    float* h1 = sh1 + tid * (HIDN + 1);   // stride 101: conflict-free across lanes

    #pragma unroll 4
    for (int k = 0; k < HIDN; k++) {
        float a = sbe1[k];
        a = fmaf(x0, sWe1[k], a);
        a = fmaf(x1, sWe1[HIDN + k], a);
        a = fmaf(x2, sWe1[2 * HIDN + k], a);
        float sig = __fdividef(1.f, 1.f + __expf(-a));
        h1[k] = a * sig;
    }
    // each thread reads only its own h1 row -> no barrier needed

    float mu0 = bmu[0], mu1 = bmu[1], ltv = blt[0];
    for (int k = 0; k < HIDN; k++) {
        float a = sbe2[k];
        const float* w = sWe2 + k;   // column k, stride HIDN (broadcast across lanes)
        #pragma unroll 4
        for (int j = 0; j < HIDN; j++)
            a = fmaf(h1[j], w[j * HIDN], a);
        float sig = __fdividef(1.f, 1.f + __expf(-a));
        float h2 = a * sig;
        mu0 = fmaf(h2, sWmu[2 * k + 0], mu0);
        mu1 = fmaf(h2, sWmu[2 * k + 1], mu1);
        ltv = fmaf(h2, sWlt[k], ltv);
    }

    out[8 * NP + 2 * p + 0] = mu0;
    out[8 * NP + 2 * p + 1] = mu1;
    out[10 * NP + p]        = ltv;
}

// ---------------------------------------------------------------------------
// SDE kernel v3: 1 thread per point (the R3 known-good mapping), inner
// j-loop restructured into groups of 4 with batched table loads and 4
// concurrent activation chains to hide MUFU/LDS latency.
// ---------------------------------------------------------------------------
__global__ void __launch_bounds__(128) sde_kernel(
    const float* __restrict__ Wd1,  const float* __restrict__ bd1,
    const float* __restrict__ Wdmu, const float* __restrict__ bdmu,
    const float* __restrict__ Wds,  const float* __restrict__ bds,
    const float* __restrict__ b_muz, const float* __restrict__ b_ltz,
    const float* __restrict__ noise,
    float* __restrict__ out)
{
    // Per-hidden-unit constant table (12 floats each, packed as 3x float4):
    // cA = {u0, u1, b, u0*u0}; cB = {u0*u1, u1*u1, wmu0, wmu1};
    // cC = {wmu2, ws0, ws1, ws2}
    __shared__ float4 cA[HIDN], cB[HIDN], cC[HIDN];

    const int tid = threadIdx.x;
    for (int j = tid; j < HIDN; j += 128) {
        float u0 = Wd1[j];
        float u1 = Wd1[HIDN + j];
        float b  = bd1[j];
        cA[j] = make_float4(u0, u1, b, u0 * u0);
        cB[j] = make_float4(u0 * u1, u1 * u1, Wdmu[j * 3 + 0], Wdmu[j * 3 + 1]);
        cC[j] = make_float4(Wdmu[j * 3 + 2], Wds[j * 3 + 0], Wds[j * 3 + 1], Wds[j * 3 + 2]);
    }
    __syncthreads();

    const int p = blockIdx.x * 128 + tid;

    float z0 = out[8 * NP + 2 * p + 0];
    float z1 = out[8 * NP + 2 * p + 1];
    const float ltv  = out[10 * NP + p];
    const float sqdt = sqrtf(__expf(2.f * ltv) * (1.0f / NSTEPS));

    const float2* __restrict__ noise2 = (const float2*)noise;

    for (int s = 0; s < NSTEPS; s++) {
        float J[6][2];
        float Bm[6][3];
        #pragma unroll
        for (int i = 0; i < 6; i++) {
            J[i][0] = 0.f; J[i][1] = 0.f;
            Bm[i][0] = 0.f; Bm[i][1] = 0.f; Bm[i][2] = 0.f;
        }

        // ---- inner reduction over hidden units, 4 at a time ----
        for (int t = 0; t < HIDN / 4; t++) {
            const int j0 = 4 * t;

            // Stage 1: batch all 12 table loads (LDS MLP)
            float4 A[4], B[4], C[4];
            #pragma unroll
            for (int q = 0; q < 4; q++) {
                A[q] = cA[j0 + q];
                B[q] = cB[j0 + q];
                C[q] = cC[j0 + q];
            }

            // Stage 2: 4 independent activation chains
            float du0[4], du1[4], e00[4], e01[4], e11[4];
            #pragma unroll
            for (int q = 0; q < 4; q++) {
                float a   = fmaf(z0, A[q].x, fmaf(z1, A[q].y, A[q].z));
                float sig = __fdividef(1.f, 1.f + __expf(-a));
                float t1  = sig * (1.f - sig);
                float d   = fmaf(a, t1, sig);                       // swish'
                float e   = t1 * fmaf(a, fmaf(-2.f, sig, 1.f), 2.f); // swish''
                du0[q] = d * A[q].x;
                du1[q] = d * A[q].y;
                e00[q] = e * A[q].w;
                e01[q] = e * B[q].x;
                e11[q] = e * B[q].y;
            }

            // Stage 3: rank-1 accumulations (independent FMA streams)
            #pragma unroll
            for (int q = 0; q < 4; q++) {
                float w[6] = { B[q].z, B[q].w, C[q].x, C[q].y, C[q].z, C[q].w };
                #pragma unroll
                for (int i = 0; i < 6; i++) {
                    J[i][0]  = fmaf(w[i], du0[q], J[i][0]);
                    J[i][1]  = fmaf(w[i], du1[q], J[i][1]);
                    Bm[i][0] = fmaf(w[i], e00[q], Bm[i][0]);
                    Bm[i][1] = fmaf(w[i], e01[q], Bm[i][1]);
                    Bm[i][2] = fmaf(w[i], e11[q], Bm[i][2]);
                }
            }
        }

        // ---- 2x2 geometry ----
        float g00 = 0.f, g01 = 0.f, g11 = 0.f;
        float Dg[2][2][2];
        #pragma unroll
        for (int k = 0; k < 2; k++)
            #pragma unroll
            for (int m = 0; m < 2; m++)
                #pragma unroll
                for (int l = 0; l < 2; l++)
                    Dg[k][m][l] = 0.f;

        #pragma unroll
        for (int i = 0; i < 6; i++) {
            g00 = fmaf(J[i][0], J[i][0], g00);
            g01 = fmaf(J[i][0], J[i][1], g01);
            g11 = fmaf(J[i][1], J[i][1], g11);
            #pragma unroll
            for (int k = 0; k < 2; k++)
                #pragma unroll
                for (int m = 0; m < 2; m++)
                    #pragma unroll
                    for (int l = 0; l < 2; l++)
                        Dg[k][m][l] += Bm[i][k + l] * J[i][m] + J[i][k] * Bm[i][m + l];
        }

        const float detg = fmaf(g00, g11, -g01 * g01);
        const float rin  = __fdividef(1.f, detg);
        float gi[2][2];
        gi[0][0] =  g11 * rin;
        gi[0][1] = -g01 * rin;
        gi[1][0] = -g01 * rin;
        gi[1][1] =  g00 * rin;

        // Christoffel: Ch[i][k][l] = 0.5*sum_m gi[i][m]*(Dg[k][m][l]+Dg[l][m][k]-Dg[k][l][m])
        float Ch[2][2][2];
        #pragma unroll
        for (int i = 0; i < 2; i++)
            #pragma unroll
            for (int k = 0; k < 2; k++)
                #pragma unroll
                for (int l = 0; l < 2; l++) {
                    float sacc = 0.f;
                    #pragma unroll
                    for (int m = 0; m < 2; m++)
                        sacc += gi[i][m] * (Dg[k][m][l] + Dg[l][m][k] - Dg[k][l][m]);
                    Ch[i][k][l] = 0.5f * sacc;
                }

        // drift[i] = 0.5 * sum_{j,k} gi[j][k] * Ch[i][j][k]
        float drift[2];
        #pragma unroll
        for (int i = 0; i < 2; i++) {
            float sacc = 0.f;
            #pragma unroll
            for (int jj = 0; jj < 2; jj++)
                #pragma unroll
                for (int kk = 0; kk < 2; kk++)
                    sacc += gi[jj][kk] * Ch[i][jj][kk];
            drift[i] = 0.5f * sacc;
        }

        const float2 nz = noise2[s * NP + p];
        const float dW0 = sqdt * nz.x;
        const float dW1 = sqdt * nz.y;

        z0 += drift[0] + gi[0][0] * dW0 + gi[0][1] * dW1;
        z1 += drift[1] + gi[1][0] * dW0 + gi[1][1] * dW1;
    }

    // Final decoder heads at z
    float mu[3] = { bdmu[0], bdmu[1], bdmu[2] };
    float ls[3] = { bds[0],  bds[1],  bds[2]  };
    #pragma unroll 4
    for (int j = 0; j < HIDN; j++) {
        const float4 a4 = cA[j];
        const float4 b4 = cB[j];
        const float4 c4 = cC[j];
        float a   = fmaf(z0, a4.x, fmaf(z1, a4.y, a4.z));
        float sig = __fdividef(1.f, 1.f + __expf(-a));
        float h   = a * sig;
        mu[0] = fmaf(h, b4.z, mu[0]);
        mu[1] = fmaf(h, b4.w, mu[1]);
        mu[2] = fmaf(h, c4.x, mu[2]);
        ls[0] = fmaf(h, c4.y, ls[0]);
        ls[1] = fmaf(h, c4.z, ls[1]);
        ls[2] = fmaf(h, c4.w, ls[2]);
    }

    // Outputs (tuple concatenation, 14*NP floats):
    // z | mu_xz | log_sigma_xz | mu_zx | log_t_zx | mu_z | log_t_z
    out[2 * p + 0] = z0;
    out[2 * p + 1] = z1;
    out[2 * NP + 3 * p + 0] = mu[0];
    out[2 * NP + 3 * p + 1] = mu[1];
    out[2 * NP + 3 * p + 2] = mu[2];
    out[5 * NP + 3 * p + 0] = ls[0];
    out[5 * NP + 3 * p + 1] = ls[1];
    out[5 * NP + 3 * p + 2] = ls[2];
    out[11 * NP + 2 * p + 0] = b_muz[0];
    out[11 * NP + 2 * p + 1] = b_muz[1];
    out[13 * NP + p] = b_ltz[0];
}

extern "C" void kernel_launch(void* const* d_in, const int* in_sizes, int n_in,
                              void* d_out, int out_size)
{
    const float* x     = (const float*)d_in[0];
    const float* We1   = (const float*)d_in[1];
    const float* be1   = (const float*)d_in[2];
    const float* We2   = (const float*)d_in[3];
    const float* be2   = (const float*)d_in[4];
    const float* Wmu   = (const float*)d_in[5];
    const float* bmu   = (const float*)d_in[6];
    const float* Wlt   = (const float*)d_in[7];
    const float* blt   = (const float*)d_in[8];
    const float* Wd1   = (const float*)d_in[9];
    const float* bd1   = (const float*)d_in[10];
    const float* Wdmu  = (const float*)d_in[11];
    const float* bdmu  = (const float*)d_in[12];
    const float* Wds   = (const float*)d_in[13];
    const float* bds   = (const float*)d_in[14];
    const float* b_muz = (const float*)d_in[15];
    const float* b_ltz = (const float*)d_in[16];
    const float* noise = (const float*)d_in[17];
    float* out = (float*)d_out;

    const size_t smem = (size_t)(10800 + 128 * (HIDN + 1)) * sizeof(float); // ~94.9 KB
    cudaFuncSetAttribute(encoder_kernel,
                         cudaFuncAttributeMaxDynamicSharedMemorySize, (int)smem);

    encoder_kernel<<<NP / 128, 128, smem>>>(x, We1, be1, We2, be2,
                                            Wmu, bmu, Wlt, blt, out);
    sde_kernel<<<NP / 128, 128>>>(Wd1, bd1, Wdmu, bdmu, Wds, bds,
                                  b_muz, b_ltz, noise, out);
}